// round 10
// baseline (speedup 1.0000x reference)
#include <cuda_runtime.h>
#include <math.h>

#define NBK  5
#define HD   32
#define DIN  4
#define TT   25
#define HIDD 64
#define TPB  128          // 4 warps
#define COLS 32           // lanes = sample columns
#define SPT  4            // samples per thread (float4-packed)
#define SPC  128          // samples per CTA
#define TILES 256         // 32768 / 128
#define GRID (TILES*NBK)  // 1280
#define JW   8            // j rows per warp
#define JB   4            // j per pass (2 passes)

typedef unsigned long long u64;

// Cross-step pipelined LSTM: iteration t computes L1(t) AND L0(t+1).
// The merged k-loop over h0(t) feeds both weight matrices from ONE state load.
// Gate rows i,f,o are pre-scaled by 0.5 so sigmoid(v) = fma(.5, tanh(acc), .5).
// h0(s) lives in buffer s&1, h1(s) in buffer s&1; one barrier per iteration.
struct SmemLayout {
    float Wh0p[HD][HD][4];    // 16384 B  (prescaled i,f,o rows)
    float Wp1p[HD][HD][4];    // 16384 B
    float Wh1p[HD][HD][4];    // 16384 B
    float bp0[HD][4];         //   512 B
    float bp1[HD][4];         //   512 B
    float4 h0s[2][HD][COLS];  // 32768 B
    float4 h1s[2][HD][COLS];  // 32768 B
};                            // 115712 B -> 2 CTAs/SM (8 warps)

// MLP overlay offsets (floats) into the weight region (reused after recurrence)
#define OV_W1 0
#define OV_B1 2048
#define OV_W2 2112
#define OV_B2 6208

// Pre-interleaved + prescaled layer-0 input weights: g_wp0[ib][k][j][gate]
__device__ __align__(16) float g_wp0[NBK][DIN][HD][4];

__global__ void prep_kernel(const float* __restrict__ Wih0) {
    const int i = blockIdx.x;
    for (int idx = threadIdx.x; idx < 4 * HD * DIN; idx += blockDim.x) {
        int r = idx / DIN, k = idx % DIN, g = r >> 5, j = r & 31;
        float s = (g == 2) ? 1.0f : 0.5f;   // prescale i,f,o
        g_wp0[i][k][j][g] = s * Wih0[i * 4 * HD * DIN + idx];
    }
}

__device__ __forceinline__ u64 pk2(float v) {
    u64 r; asm("mov.b64 %0, {%1, %1};" : "=l"(r) : "f"(v)); return r;
}
__device__ __forceinline__ u64 f2fma(u64 a, u64 b, u64 c) {
    u64 d; asm("fma.rn.f32x2 %0, %1, %2, %3;" : "=l"(d) : "l"(a), "l"(b), "l"(c));
    return d;
}
__device__ __forceinline__ void unpk(u64 v, float& lo, float& hi) {
    asm("mov.b64 {%0, %1}, %2;" : "=f"(lo), "=f"(hi) : "l"(v));
}
__device__ __forceinline__ float tanhfast(float x) {
    float y; asm("tanh.approx.f32 %0, %1;" : "=f"(y) : "f"(x)); return y;
}
// sigmoid of a PRESCALED preactivation (acc already = v/2)
__device__ __forceinline__ float sigp(float v) {
    return fmaf(0.5f, tanhfast(v), 0.5f);
}

__global__ void __launch_bounds__(TPB, 2) lstm_fused(
    const float* __restrict__ x,    const float* __restrict__ mask,
    const float* __restrict__ Wih0, const float* __restrict__ Whh0,
    const float* __restrict__ bih0, const float* __restrict__ bhh0,
    const float* __restrict__ Wih1, const float* __restrict__ Whh1,
    const float* __restrict__ bih1, const float* __restrict__ bhh1,
    const float* __restrict__ W1,   const float* __restrict__ b1,
    const float* __restrict__ W2,   const float* __restrict__ b2,
    float* __restrict__ out)
{
    extern __shared__ float smraw[];
    SmemLayout* S = reinterpret_cast<SmemLayout*>(smraw);
    const int tid   = threadIdx.x;
    const int lane  = tid & 31;
    const int jbase = (tid >> 5) * JW;
    const int ib    = 4 - (blockIdx.x >> 8);        // heavy blocks first
    const int tile  = blockIdx.x & (TILES - 1);

    // ---- stage weights into SMEM (interleaved, i/f/o prescaled by 0.5) ----
    {
        const float* whh0 = Whh0 + ib * 4 * HD * HD;
        const float* wih1 = Wih1 + ib * 4 * HD * HD;
        const float* whh1 = Whh1 + ib * 4 * HD * HD;
        for (int idx = tid; idx < 4 * HD * HD; idx += TPB) {
            int r = idx / HD, k = idx % HD, g = r >> 5, j = r & 31;
            float s = (g == 2) ? 1.0f : 0.5f;
            S->Wh0p[k][j][g] = s * whh0[idx];
            S->Wp1p[k][j][g] = s * wih1[idx];
            S->Wh1p[k][j][g] = s * whh1[idx];
        }
        for (int idx = tid; idx < 4 * HD; idx += TPB) {
            int g = idx >> 5, j = idx & 31;
            float s = (g == 2) ? 1.0f : 0.5f;
            S->bp0[j][g] = s * (bih0[ib * 4 * HD + idx] + bhh0[ib * 4 * HD + idx]);
            S->bp1[j][g] = s * (bih1[ib * 4 * HD + idx] + bhh1[ib * 4 * HD + idx]);
        }
        // zero h1 buffer 1 (read as h1(-1) in iter 0); other buffers write-before-read
        float4* st1 = reinterpret_cast<float4*>(&S->h1s[1][0][0]);
        for (int i = tid; i < HD * COLS; i += TPB) st1[i] = make_float4(0.f, 0.f, 0.f, 0.f);
    }

    float c0r[JW][SPT], c1r[JW][SPT];
#pragma unroll
    for (int q = 0; q < JW; q++)
#pragma unroll
        for (int s4 = 0; s4 < SPT; s4++) { c0r[q][s4] = 0.0f; c1r[q][s4] = 0.0f; }

    const int Ti = 5 * (ib + 1);
    const float4* xb = reinterpret_cast<const float4*>(x)    + (size_t)(tile * SPC + lane) * TT + (TT - Ti);
    const float4* mb = reinterpret_cast<const float4*>(mask) + (size_t)(tile * SPC + lane) * TT + (TT - Ti);

    __syncthreads();   // weights + h1 zeros visible

    // ---- prologue: L0(0) = bias + x(0)-term (h0_init = 0), write h0(0) -> buf 0 ----
    {
        float xmf[SPT][DIN];
#pragma unroll
        for (int s4 = 0; s4 < SPT; s4++) {
            float4 xv = __ldg(xb + (size_t)s4 * COLS * TT);
            float4 mv = __ldg(mb + (size_t)s4 * COLS * TT);
            xmf[s4][0] = xv.x * mv.x; xmf[s4][1] = xv.y * mv.y;
            xmf[s4][2] = xv.z * mv.z; xmf[s4][3] = xv.w * mv.w;
        }
#pragma unroll
        for (int p = 0; p < JW / JB; p++) {
            u64 aI[SPT][JB], aG[SPT][JB];
#pragma unroll
            for (int q = 0; q < JB; q++) {
                ulonglong2 bb = *reinterpret_cast<const ulonglong2*>(S->bp0[jbase + p * JB + q]);
#pragma unroll
                for (int s4 = 0; s4 < SPT; s4++) { aI[s4][q] = bb.x; aG[s4][q] = bb.y; }
            }
#pragma unroll
            for (int k = 0; k < DIN; k++) {
                u64 hx[SPT];
#pragma unroll
                for (int s4 = 0; s4 < SPT; s4++) hx[s4] = pk2(xmf[s4][k]);
#pragma unroll
                for (int q = 0; q < JB; q++) {
                    ulonglong2 w = __ldg(reinterpret_cast<const ulonglong2*>(
                        &g_wp0[ib][k][jbase + p * JB + q][0]));
#pragma unroll
                    for (int s4 = 0; s4 < SPT; s4++) {
                        aI[s4][q] = f2fma(w.x, hx[s4], aI[s4][q]);
                        aG[s4][q] = f2fma(w.y, hx[s4], aG[s4][q]);
                    }
                }
            }
#pragma unroll
            for (int q = 0; q < JB; q++) {
                const int idx = p * JB + q;
                float hv[SPT];
#pragma unroll
                for (int s4 = 0; s4 < SPT; s4++) {
                    float ai, af, ag, ao;
                    unpk(aI[s4][q], ai, af); unpk(aG[s4][q], ag, ao);
                    float cc = sigp(af) * c0r[idx][s4] + sigp(ai) * tanhfast(ag);
                    c0r[idx][s4] = cc;
                    hv[s4] = sigp(ao) * tanhfast(cc);
                }
                S->h0s[0][jbase + idx][lane] = make_float4(hv[0], hv[1], hv[2], hv[3]);
            }
        }
    }
    __syncthreads();   // h0(0) visible

    // ---- main loop: iter t computes L1(t) + L0(t+1) ----
    for (int st = 0; st < Ti; st++) {
        const int rb0 = st & 1, wb0 = 1 - rb0;   // h0(t) / h0(t+1)
        const int rb1 = wb0,    wb1 = rb0;       // h1(t-1) / h1(t)

        // x(t+1), clamped on the final (dead) iteration
        const int xi = (st + 1 < Ti) ? (st + 1) : (Ti - 1);
        float4 xvv[SPT], mvv[SPT];
#pragma unroll
        for (int s4 = 0; s4 < SPT; s4++) {
            xvv[s4] = __ldg(xb + (size_t)s4 * COLS * TT + xi);
            mvv[s4] = __ldg(mb + (size_t)s4 * COLS * TT + xi);
        }

#pragma unroll
        for (int p = 0; p < JW / JB; p++) {
            u64 aI0[SPT][JB], aG0[SPT][JB], aI1[SPT][JB], aG1[SPT][JB];
#pragma unroll
            for (int q = 0; q < JB; q++) {
                ulonglong2 b0 = *reinterpret_cast<const ulonglong2*>(S->bp0[jbase + p * JB + q]);
                ulonglong2 b1v = *reinterpret_cast<const ulonglong2*>(S->bp1[jbase + p * JB + q]);
#pragma unroll
                for (int s4 = 0; s4 < SPT; s4++) {
                    aI0[s4][q] = b0.x;  aG0[s4][q] = b0.y;
                    aI1[s4][q] = b1v.x; aG1[s4][q] = b1v.y;
                }
            }

            // ---- merged k-loop over h0(t): feeds Wh0 (L0 t+1) and Wp1 (L1 t) ----
#pragma unroll 8
            for (int k = 0; k < HD; k++) {
                float4 hv = S->h0s[rb0][k][lane];
                u64 hh[SPT];
                hh[0] = pk2(hv.x); hh[1] = pk2(hv.y); hh[2] = pk2(hv.z); hh[3] = pk2(hv.w);
#pragma unroll
                for (int q = 0; q < JB; q++) {
                    ulonglong2 w0 = *reinterpret_cast<const ulonglong2*>(S->Wh0p[k][jbase + p * JB + q]);
                    ulonglong2 w1 = *reinterpret_cast<const ulonglong2*>(S->Wp1p[k][jbase + p * JB + q]);
#pragma unroll
                    for (int s4 = 0; s4 < SPT; s4++) {
                        aI0[s4][q] = f2fma(w0.x, hh[s4], aI0[s4][q]);
                        aG0[s4][q] = f2fma(w0.y, hh[s4], aG0[s4][q]);
                        aI1[s4][q] = f2fma(w1.x, hh[s4], aI1[s4][q]);
                        aG1[s4][q] = f2fma(w1.y, hh[s4], aG1[s4][q]);
                    }
                }
            }

            // ---- DIN loop for L0(t+1) ----
            {
                float xmf[SPT][DIN];
#pragma unroll
                for (int s4 = 0; s4 < SPT; s4++) {
                    xmf[s4][0] = xvv[s4].x * mvv[s4].x; xmf[s4][1] = xvv[s4].y * mvv[s4].y;
                    xmf[s4][2] = xvv[s4].z * mvv[s4].z; xmf[s4][3] = xvv[s4].w * mvv[s4].w;
                }
#pragma unroll
                for (int k = 0; k < DIN; k++) {
                    u64 hx[SPT];
#pragma unroll
                    for (int s4 = 0; s4 < SPT; s4++) hx[s4] = pk2(xmf[s4][k]);
#pragma unroll
                    for (int q = 0; q < JB; q++) {
                        ulonglong2 w = __ldg(reinterpret_cast<const ulonglong2*>(
                            &g_wp0[ib][k][jbase + p * JB + q][0]));
#pragma unroll
                        for (int s4 = 0; s4 < SPT; s4++) {
                            aI0[s4][q] = f2fma(w.x, hx[s4], aI0[s4][q]);
                            aG0[s4][q] = f2fma(w.y, hx[s4], aG0[s4][q]);
                        }
                    }
                }
            }

            // ---- L0(t+1) epilogue (MUFU) -- interleaves with h1 FFMA loop below ----
#pragma unroll
            for (int q = 0; q < JB; q++) {
                const int idx = p * JB + q;
                float hv[SPT];
#pragma unroll
                for (int s4 = 0; s4 < SPT; s4++) {
                    float ai, af, ag, ao;
                    unpk(aI0[s4][q], ai, af); unpk(aG0[s4][q], ag, ao);
                    float cc = sigp(af) * c0r[idx][s4] + sigp(ai) * tanhfast(ag);
                    c0r[idx][s4] = cc;
                    hv[s4] = sigp(ao) * tanhfast(cc);
                }
                S->h0s[wb0][jbase + idx][lane] = make_float4(hv[0], hv[1], hv[2], hv[3]);
            }

            // ---- h1(t-1) k-loop for L1(t) ----
#pragma unroll 8
            for (int k = 0; k < HD; k++) {
                float4 hv = S->h1s[rb1][k][lane];
                u64 hh[SPT];
                hh[0] = pk2(hv.x); hh[1] = pk2(hv.y); hh[2] = pk2(hv.z); hh[3] = pk2(hv.w);
#pragma unroll
                for (int q = 0; q < JB; q++) {
                    ulonglong2 w = *reinterpret_cast<const ulonglong2*>(S->Wh1p[k][jbase + p * JB + q]);
#pragma unroll
                    for (int s4 = 0; s4 < SPT; s4++) {
                        aI1[s4][q] = f2fma(w.x, hh[s4], aI1[s4][q]);
                        aG1[s4][q] = f2fma(w.y, hh[s4], aG1[s4][q]);
                    }
                }
            }

            // ---- L1(t) epilogue ----
#pragma unroll
            for (int q = 0; q < JB; q++) {
                const int idx = p * JB + q;
                float hv[SPT];
#pragma unroll
                for (int s4 = 0; s4 < SPT; s4++) {
                    float ai, af, ag, ao;
                    unpk(aI1[s4][q], ai, af); unpk(aG1[s4][q], ag, ao);
                    float cc = sigp(af) * c1r[idx][s4] + sigp(ai) * tanhfast(ag);
                    c1r[idx][s4] = cc;
                    hv[s4] = sigp(ao) * tanhfast(cc);
                }
                S->h1s[wb1][jbase + idx][lane] = make_float4(hv[0], hv[1], hv[2], hv[3]);
            }
        }
        __syncthreads();   // h0(t+1), h1(t) visible for iter t+1
    }

    // ---- MLP head: 1 thread per sample ----
    const int fb = (Ti - 1) & 1;   // buffer holding h1(Ti-1)

    float* ov = smraw;
    for (int idx = tid; idx < HIDD * HD; idx += TPB)   ov[OV_W1 + idx] = W1[idx];
    for (int idx = tid; idx < HIDD * HIDD; idx += TPB) {
        int n = idx / HIDD, m = idx % HIDD;
        ov[OV_W2 + m * HIDD + n] = W2[idx];            // transposed [m][n]
    }
    if (tid < HIDD) { ov[OV_B1 + tid] = b1[tid]; ov[OV_B2 + tid] = b2[tid]; }
    __syncthreads();

    const int scol = tid & 31;
    const int sq   = tid >> 5;

    float hr[HD];
#pragma unroll
    for (int k = 0; k < HD; k++) {
        float4 v = S->h1s[fb][k][scol];
        hr[k] = (sq == 0) ? v.x : (sq == 1) ? v.y : (sq == 2) ? v.z : v.w;
    }

    float acc2[HIDD];
#pragma unroll
    for (int n = 0; n < HIDD; n++) acc2[n] = ov[OV_B2 + n];

    for (int m = 0; m < HIDD; m++) {
        float tm = ov[OV_B1 + m];
        const float4* w1r = reinterpret_cast<const float4*>(&ov[OV_W1 + m * HD]);
#pragma unroll
        for (int q = 0; q < HD / 4; q++) {
            float4 w = w1r[q];
            tm += hr[4 * q + 0] * w.x + hr[4 * q + 1] * w.y
                + hr[4 * q + 2] * w.z + hr[4 * q + 3] * w.w;
        }
        tm = 0.5f * tm * (1.0f + erff(tm * 0.70710678118654752f));   // exact gelu
        const float4* w2r = reinterpret_cast<const float4*>(&ov[OV_W2 + m * HIDD]);
#pragma unroll
        for (int q = 0; q < HIDD / 4; q++) {
            float4 w = w2r[q];
            acc2[4 * q + 0] += tm * w.x; acc2[4 * q + 1] += tm * w.y;
            acc2[4 * q + 2] += tm * w.z; acc2[4 * q + 3] += tm * w.w;
        }
    }

    const int bS = tile * SPC + sq * COLS + scol;
    float4* op = reinterpret_cast<float4*>(out + ((size_t)bS * NBK + ib) * HIDD);
#pragma unroll
    for (int q = 0; q < HIDD / 4; q++)
        op[q] = make_float4(acc2[4 * q], acc2[4 * q + 1],
                            acc2[4 * q + 2], acc2[4 * q + 3]);
}

extern "C" void kernel_launch(void* const* d_in, const int* in_sizes, int n_in,
                              void* d_out, int out_size)
{
    const float* x    = (const float*)d_in[0];
    const float* mask = (const float*)d_in[1];
    const float* Wih0 = (const float*)d_in[2];
    const float* Whh0 = (const float*)d_in[3];
    const float* bih0 = (const float*)d_in[4];
    const float* bhh0 = (const float*)d_in[5];
    const float* Wih1 = (const float*)d_in[6];
    const float* Whh1 = (const float*)d_in[7];
    const float* bih1 = (const float*)d_in[8];
    const float* bhh1 = (const float*)d_in[9];
    const float* W1   = (const float*)d_in[10];
    const float* b1   = (const float*)d_in[11];
    const float* W2   = (const float*)d_in[12];
    const float* b2   = (const float*)d_in[13];
    float* out = (float*)d_out;

    prep_kernel<<<NBK, 128>>>(Wih0);   // interleave + prescale Wp0 (graph-safe)

    const size_t smem = sizeof(SmemLayout);   // 115712 B -> 2 CTAs/SM
    cudaFuncSetAttribute(lstm_fused, cudaFuncAttributeMaxDynamicSharedMemorySize,
                         (int)smem);
    lstm_fused<<<GRID, TPB, smem>>>(x, mask, Wih0, Whh0, bih0, bhh0,
                                    Wih1, Whh1, bih1, bhh1, W1, b1, W2, b2, out);
}